// round 12
// baseline (speedup 1.0000x reference)
#include <cuda_runtime.h>
#include <math.h>
#include <float.h>

#define NB 64
#define LL 196
#define AA 512
#define HH 512
#define EE 512
#define VV 30000
#define TT 20

// ---- device scratch (no cudaMalloc allowed) ----
__device__ __align__(16) float g_mean [NB*AA];
__device__ __align__(16) float g_h    [NB*HH];
__device__ __align__(16) float g_c    [NB*HH];
__device__ __align__(16) float g_hlWa [NB*LL*HH];
__device__ __align__(16) float g_x    [NB*(AA+EE)];
__device__ __align__(16) float g_gpart[3*NB*4*HH];
__device__ __align__(16) int   g_tok  [NB];
__device__ __align__(16) unsigned long long g_amax[NB];

__device__ __forceinline__ float sigf(float x) { return 1.0f / (1.0f + expf(-x)); }

// ---- f32x2 helpers (Blackwell packed FMA) ----
__device__ __forceinline__ unsigned long long pk2(float x, float y) {
    unsigned long long r;
    asm("mov.b64 %0, {%1, %2};" : "=l"(r) : "f"(x), "f"(y));
    return r;
}
__device__ __forceinline__ void fma2(unsigned long long& d, unsigned long long a, unsigned long long b) {
    asm("fma.rn.f32x2 %0, %1, %2, %0;" : "+l"(d) : "l"(a), "l"(b));
}
__device__ __forceinline__ float2 upk2(unsigned long long v) {
    float2 r;
    asm("mov.b64 {%0, %1}, %2;" : "=f"(r.x), "=f"(r.y) : "l"(v));
    return r;
}
__device__ __forceinline__ unsigned int ordf(float f) {
    unsigned int u = __float_as_uint(f);
    return (u & 0x80000000u) ? ~u : (u | 0x80000000u);
}

// =====================================================================
// M=64 tiled GEMM core, f32x2 accumulate.
// C[64, 64-col tile] = act(A[64,512] @ B[512,ldb] + bias)
// 256 thr; thread = 8 rows (4 row-pairs) x 2 cols.
// =====================================================================
template<int ACT>
__device__ __forceinline__ void gemm64_core(
    float (&As)[32][72], float (&Bs)[32][64],
    const float* __restrict__ A, int lda,
    const float* __restrict__ B, int ldb, int colOff,
    float* __restrict__ C, int ldc, const float* __restrict__ bias)
{
    const int tid  = threadIdx.x;
    const int lane = tid & 31, w = tid >> 5;
    const int r0   = w * 8;
    unsigned long long acc[2][4];
#pragma unroll
    for (int j = 0; j < 2; j++)
#pragma unroll
        for (int p = 0; p < 4; p++) acc[j][p] = 0ULL;

    for (int kc = 0; kc < 512; kc += 32) {
        {   // stage A transposed
            int r = tid >> 2, kb = (tid & 3) * 8;
            const float* s = A + r * lda + kc + kb;
            float4 v0 = *(const float4*)s;
            float4 v1 = *(const float4*)(s + 4);
            As[kb+0][r] = v0.x; As[kb+1][r] = v0.y; As[kb+2][r] = v0.z; As[kb+3][r] = v0.w;
            As[kb+4][r] = v1.x; As[kb+5][r] = v1.y; As[kb+6][r] = v1.z; As[kb+7][r] = v1.w;
        }
        {   // stage B
            int kk = tid >> 3, cb = (tid & 7) * 8;
            const float* s = B + (kc + kk) * ldb + colOff + cb;
            *(float4*)&Bs[kk][cb]     = *(const float4*)s;
            *(float4*)&Bs[kk][cb + 4] = *(const float4*)(s + 4);
        }
        __syncthreads();
#pragma unroll
        for (int k = 0; k < 32; k++) {
            const unsigned long long* ap = (const unsigned long long*)&As[k][r0];
            unsigned long long a0 = ap[0], a1 = ap[1], a2 = ap[2], a3 = ap[3];
            float2 b = *(const float2*)&Bs[k][lane * 2];
            unsigned long long bb0 = pk2(b.x, b.x), bb1 = pk2(b.y, b.y);
            fma2(acc[0][0], a0, bb0); fma2(acc[0][1], a1, bb0);
            fma2(acc[0][2], a2, bb0); fma2(acc[0][3], a3, bb0);
            fma2(acc[1][0], a0, bb1); fma2(acc[1][1], a1, bb1);
            fma2(acc[1][2], a2, bb1); fma2(acc[1][3], a3, bb1);
        }
        __syncthreads();
    }
#pragma unroll
    for (int j = 0; j < 2; j++) {
        int col = colOff + lane * 2 + j;
        float bv = bias ? bias[col] : 0.0f;
#pragma unroll
        for (int p = 0; p < 4; p++) {
            float2 v = upk2(acc[j][p]);
            float x = v.x + bv, y = v.y + bv;
            if (ACT == 1) { x = tanhf(x); y = tanhf(y); }
            C[(r0 + 2*p    ) * ldc + col] = x;
            C[(r0 + 2*p + 1) * ldc + col] = y;
        }
    }
}

// ---- precompute ----
__global__ __launch_bounds__(256) void kernel_mean(const float* __restrict__ hl) {
    int n = blockIdx.x, tid = threadIdx.x;
    float s0 = 0.f, s1 = 0.f;
    for (int l = 0; l < LL; l++) {
        const float* row = hl + (n * LL + l) * AA;
        s0 += row[tid]; s1 += row[tid + 256];
    }
    g_mean[n * AA + tid]       = s0 / 196.0f;
    g_mean[n * AA + tid + 256] = s1 / 196.0f;
    if (tid == 0) { g_tok[n] = 1; g_amax[n] = 0ULL; }
}

__global__ __launch_bounds__(256) void kernel_init_hc(
    const float* __restrict__ Wh0, const float* __restrict__ bh0,
    const float* __restrict__ Wc0, const float* __restrict__ bc0)
{
    __shared__ __align__(16) float As[32][72];
    __shared__ __align__(16) float Bs[32][64];
    int colOff = blockIdx.x * 64;
    if (blockIdx.y == 0)
        gemm64_core<1>(As, Bs, g_mean, AA, Wh0, HH, colOff, g_h, HH, bh0);
    else
        gemm64_core<1>(As, Bs, g_mean, AA, Wc0, HH, colOff, g_c, HH, bc0);
}

__global__ __launch_bounds__(256) void kernel_hlwa(
    const float* __restrict__ hl, const float* __restrict__ Wa)
{
    __shared__ __align__(16) float As[32][72];
    __shared__ __align__(16) float Bs[32][64];
    int rowOff = blockIdx.y * 64;
    gemm64_core<0>(As, Bs, hl + rowOff * AA, AA, Wa, HH,
                   blockIdx.x * 64, g_hlWa + rowOff * HH, HH, (const float*)0);
}

// ---- per step: attention with fused hUa = h@Ua + ba ----
__global__ __launch_bounds__(256) void kernel_attn(
    const float* __restrict__ hl, const float* __restrict__ Ua,
    const float* __restrict__ ba, const float* __restrict__ va,
    const float* __restrict__ Wb, const float* __restrict__ bb,
    const float* __restrict__ emb)
{
    __shared__ float sh_h[HH], sh_u[HH], sh_va[HH];
    __shared__ float sh_e[200];
    __shared__ float red[8];
    __shared__ float sc[2];
    int n = blockIdx.x, tid = threadIdx.x;
    int w = tid >> 5, lane = tid & 31;

    sh_h[tid]        = g_h[n*HH + tid];
    sh_h[tid + 256]  = g_h[n*HH + tid + 256];
    sh_va[tid]       = va[tid];
    sh_va[tid + 256] = va[tid + 256];
    __syncthreads();

    // beta partial
    float p = sh_h[tid] * Wb[tid] + sh_h[tid + 256] * Wb[tid + 256];
#pragma unroll
    for (int o = 16; o > 0; o >>= 1) p += __shfl_xor_sync(0xffffffffu, p, o);
    if (lane == 0) red[w] = p;

    // hUa: this thread computes cols 2*tid, 2*tid+1
    float2 uacc = make_float2(0.f, 0.f);
    {
        const float2* Ua2 = (const float2*)Ua;   // [512][256] float2
#pragma unroll 8
        for (int k = 0; k < HH; k++) {
            float hk = sh_h[k];
            float2 wv = Ua2[k * 256 + tid];
            uacc.x = fmaf(hk, wv.x, uacc.x);
            uacc.y = fmaf(hk, wv.y, uacc.y);
        }
    }
    __syncthreads();
    if (tid == 0) {
        float s = 0.f;
#pragma unroll
        for (int i = 0; i < 8; i++) s += red[i];
        sc[1] = sigf(s + bb[0]);
    }
    sh_u[2*tid]     = uacc.x + ba[2*tid];
    sh_u[2*tid + 1] = uacc.y + ba[2*tid + 1];
    __syncthreads();

    // e[l] = sum_k va[k]*tanh(hlWa + hUa)
    for (int l = w; l < LL; l += 8) {
        const float* row = g_hlWa + (n * LL + l) * HH;
        float s = 0.f;
        for (int k = lane; k < HH; k += 32)
            s += sh_va[k] * tanhf(row[k] + sh_u[k]);
#pragma unroll
        for (int o = 16; o > 0; o >>= 1) s += __shfl_xor_sync(0xffffffffu, s, o);
        if (lane == 0) sh_e[l] = s;
    }
    __syncthreads();

    {   // softmax over 196
        float m = (tid < LL) ? sh_e[tid] : -1e30f;
#pragma unroll
        for (int o = 16; o > 0; o >>= 1) m = fmaxf(m, __shfl_xor_sync(0xffffffffu, m, o));
        if (lane == 0) red[w] = m;
        __syncthreads();
        if (tid == 0) {
            float mm = red[0];
#pragma unroll
            for (int i = 1; i < 8; i++) mm = fmaxf(mm, red[i]);
            sc[0] = mm;
        }
        __syncthreads();
        float ex = 0.f;
        if (tid < LL) { ex = expf(sh_e[tid] - sc[0]); sh_e[tid] = ex; }
        float s = ex;
#pragma unroll
        for (int o = 16; o > 0; o >>= 1) s += __shfl_xor_sync(0xffffffffu, s, o);
        if (lane == 0) red[w] = s;
        __syncthreads();
        if (tid == 0) {
            float ss = 0.f;
#pragma unroll
            for (int i = 0; i < 8; i++) ss += red[i];
            sc[0] = ss;
        }
        __syncthreads();
        if (tid < LL) sh_e[tid] = sh_e[tid] / sc[0];
        __syncthreads();
    }

    float beta = sc[1];
    for (int a = tid; a < AA; a += 256) {
        float s = 0.f;
#pragma unroll 4
        for (int l = 0; l < LL; l++)
            s += sh_e[l] * hl[(n * LL + l) * AA + a];
        g_x[n * (AA+EE) + a] = s * beta;
    }
    int tk = g_tok[n];
    for (int j = tid; j < EE; j += 256)
        g_x[n * (AA+EE) + AA + j] = emb[tk * EE + j];
}

__global__ __launch_bounds__(256) void kernel_gates(
    const float* __restrict__ Wx, const float* __restrict__ Wh)
{
    __shared__ __align__(16) float As[32][72];
    __shared__ __align__(16) float Bs[32][64];
    int z = blockIdx.y;
    const float* A; int lda; const float* B;
    if (z < 2) { A = g_x + z * 512; lda = AA + EE; B = Wx + z * 512 * (4*HH); }
    else       { A = g_h;           lda = HH;      B = Wh; }
    gemm64_core<0>(As, Bs, A, lda, B, 4*HH, blockIdx.x * 64,
                   g_gpart + z * NB * 4 * HH, 4*HH, (const float*)0);
}

__global__ __launch_bounds__(128) void kernel_lstm(const float* __restrict__ b_lstm) {
    int n = blockIdx.x;
    const float* p0 = g_gpart + 0 * NB * 4*HH + n * 4*HH;
    const float* p1 = g_gpart + 1 * NB * 4*HH + n * 4*HH;
    const float* p2 = g_gpart + 2 * NB * 4*HH + n * 4*HH;
    for (int j = threadIdx.x; j < HH; j += 128) {
        float iv = p0[j]      + p1[j]      + p2[j]      + b_lstm[j];
        float fv = p0[j+512]  + p1[j+512]  + p2[j+512]  + b_lstm[j+512];
        float gv = p0[j+1024] + p1[j+1024] + p2[j+1024] + b_lstm[j+1024];
        float ov = p0[j+1536] + p1[j+1536] + p2[j+1536] + b_lstm[j+1536];
        float c  = sigf(fv) * g_c[n*HH + j] + sigf(iv) * tanhf(gv);
        g_c[n*HH + j] = c;
        g_h[n*HH + j] = sigf(ov) * tanhf(c);
    }
}

// logits GEMM + fused per-row argmax (atomicMax on packed keys)
__global__ __launch_bounds__(256) void kernel_logits(
    const float* __restrict__ Wout, const float* __restrict__ bout)
{
    __shared__ __align__(16) float As[32][72];
    __shared__ __align__(16) float Bs[32][64];
    const int colOff = blockIdx.x * 64;
    const int tid = threadIdx.x;
    const int lane = tid & 31, w = tid >> 5;
    const int r0 = w * 8;
    unsigned long long acc[2][4];
#pragma unroll
    for (int j = 0; j < 2; j++)
#pragma unroll
        for (int p = 0; p < 4; p++) acc[j][p] = 0ULL;

    for (int kc = 0; kc < 512; kc += 32) {
        {
            int r = tid >> 2, kb = (tid & 3) * 8;
            const float* s = g_h + r * HH + kc + kb;
            float4 v0 = *(const float4*)s;
            float4 v1 = *(const float4*)(s + 4);
            As[kb+0][r] = v0.x; As[kb+1][r] = v0.y; As[kb+2][r] = v0.z; As[kb+3][r] = v0.w;
            As[kb+4][r] = v1.x; As[kb+5][r] = v1.y; As[kb+6][r] = v1.z; As[kb+7][r] = v1.w;
        }
        {
            int kk = tid >> 3, cb = (tid & 7) * 8;
            int col = colOff + cb;
            if (col + 8 <= VV) {
                const float* s = Wout + (kc + kk) * VV + col;
                *(float4*)&Bs[kk][cb]     = *(const float4*)s;
                *(float4*)&Bs[kk][cb + 4] = *(const float4*)(s + 4);
            } else {
                float4 z = make_float4(0.f,0.f,0.f,0.f);
                *(float4*)&Bs[kk][cb] = z; *(float4*)&Bs[kk][cb + 4] = z;
            }
        }
        __syncthreads();
#pragma unroll
        for (int k = 0; k < 32; k++) {
            const unsigned long long* ap = (const unsigned long long*)&As[k][r0];
            unsigned long long a0 = ap[0], a1 = ap[1], a2 = ap[2], a3 = ap[3];
            float2 b = *(const float2*)&Bs[k][lane * 2];
            unsigned long long bb0 = pk2(b.x, b.x), bb1 = pk2(b.y, b.y);
            fma2(acc[0][0], a0, bb0); fma2(acc[0][1], a1, bb0);
            fma2(acc[0][2], a2, bb0); fma2(acc[0][3], a3, bb0);
            fma2(acc[1][0], a0, bb1); fma2(acc[1][1], a1, bb1);
            fma2(acc[1][2], a2, bb1); fma2(acc[1][3], a3, bb1);
        }
        __syncthreads();
    }

    // fused argmax epilogue: key = ordf(val)<<32 | (0xFFFFFFFF - col)
    const int c0 = colOff + lane * 2;
    const int c1 = c0 + 1;
    const bool v0ok = (c0 < VV), v1ok = (c1 < VV);
    const float b0 = v0ok ? bout[c0] : 0.f;
    const float b1 = v1ok ? bout[c1] : 0.f;
#pragma unroll
    for (int p = 0; p < 4; p++) {
        float2 a0 = upk2(acc[0][p]);   // col c0, rows r0+2p, r0+2p+1
        float2 a1 = upk2(acc[1][p]);   // col c1
#pragma unroll
        for (int q = 0; q < 2; q++) {
            float va0 = (q == 0 ? a0.x : a0.y) + b0;
            float va1 = (q == 0 ? a1.x : a1.y) + b1;
            unsigned long long k0 = v0ok ?
                (((unsigned long long)ordf(va0) << 32) | (unsigned)(0xFFFFFFFFu - (unsigned)c0)) : 0ULL;
            unsigned long long k1 = v1ok ?
                (((unsigned long long)ordf(va1) << 32) | (unsigned)(0xFFFFFFFFu - (unsigned)c1)) : 0ULL;
            unsigned long long kk = k0 > k1 ? k0 : k1;
#pragma unroll
            for (int o = 16; o > 0; o >>= 1) {
                unsigned long long ot = __shfl_xor_sync(0xffffffffu, kk, o);
                if (ot > kk) kk = ot;
            }
            if (lane == 0) atomicMax(&g_amax[r0 + 2*p + q], kk);
        }
    }
}

__global__ void kernel_finalize(float* __restrict__ out, int t) {
    int n = threadIdx.x;  // 64 threads
    unsigned long long key = g_amax[n];
    int col = (int)(0xFFFFFFFFu - (unsigned)(key & 0xFFFFFFFFull));
    if (col < 0 || col >= VV) col = 0;
    g_tok[n] = col;
    out[n * TT + t] = (float)col;   // float32 output dtype
    g_amax[n] = 0ULL;
}

extern "C" void kernel_launch(void* const* d_in, const int* in_sizes, int n_in,
                              void* d_out, int out_size) {
    static const int dict_sz[17] = {
        6422528, 15360000, 262144, 512, 262144, 512, 262144, 262144, 512, 512,
        512, 1, 2097152, 1048576, 2048, 15360000, 30000 };
    static const int alpha_sz[17] = {
        262144, 262144, 512, 262144, 1048576, 262144, 15360000, 2097152, 2048,
        512, 6422528, 1, 512, 512, 30000, 15360000, 512 };
    static const int alpha_map[17] = {10,15,5,13,3,12,1,0,9,16,2,11,7,4,8,6,14};

    int m[17];
    for (int i = 0; i < 17; i++) m[i] = i;
    if (n_in >= 17) {
        bool is_dict = true, is_alpha = true;
        for (int i = 0; i < 17; i++) {
            if (in_sizes[i] != dict_sz[i])  is_dict = false;
            if (in_sizes[i] != alpha_sz[i]) is_alpha = false;
        }
        if (is_dict) {
        } else if (is_alpha) {
            for (int i = 0; i < 17; i++) m[i] = alpha_map[i];
        } else {
            for (int i = 0; i < 17; i++) {
                int s = dict_sz[i], r = 0;
                for (int j = 0; j < i; j++) if (dict_sz[j] == s) r++;
                int seen = 0, pick = i;
                for (int k = 0; k < n_in && k < 64; k++) {
                    if (in_sizes[k] == s) {
                        if (seen == r) { pick = k; break; }
                        seen++;
                    }
                }
                m[i] = pick;
            }
        }
    }

    const float* hl     = (const float*)d_in[m[0]];
    const float* emb    = (const float*)d_in[m[1]];
    const float* Wh0    = (const float*)d_in[m[2]];
    const float* bh0    = (const float*)d_in[m[3]];
    const float* Wc0    = (const float*)d_in[m[4]];
    const float* bc0    = (const float*)d_in[m[5]];
    const float* Wa     = (const float*)d_in[m[6]];
    const float* Ua     = (const float*)d_in[m[7]];
    const float* ba     = (const float*)d_in[m[8]];
    const float* va     = (const float*)d_in[m[9]];
    const float* Wb     = (const float*)d_in[m[10]];
    const float* bb     = (const float*)d_in[m[11]];
    const float* Wx     = (const float*)d_in[m[12]];
    const float* Wh     = (const float*)d_in[m[13]];
    const float* b_lstm = (const float*)d_in[m[14]];
    const float* Wout   = (const float*)d_in[m[15]];
    const float* bout   = (const float*)d_in[m[16]];
    float* out = (float*)d_out;

    kernel_mean<<<NB, 256>>>(hl);
    kernel_init_hc<<<dim3(8, 2), 256>>>(Wh0, bh0, Wc0, bc0);
    kernel_hlwa<<<dim3(8, 196), 256>>>(hl, Wa);

    for (int t = 0; t < TT; t++) {
        kernel_attn<<<NB, 256>>>(hl, Ua, ba, va, Wb, bb, emb);
        kernel_gates<<<dim3(32, 3), 256>>>(Wx, Wh);
        kernel_lstm<<<NB, 128>>>(b_lstm);
        kernel_logits<<<(VV + 63) / 64, 256>>>(Wout, bout);
        kernel_finalize<<<1, 64>>>(out, t);
    }
}

// round 13
// speedup vs baseline: 1.9097x; 1.9097x over previous
#include <cuda_runtime.h>
#include <math.h>
#include <float.h>

#define NB 64
#define LL 196
#define AA 512
#define HH 512
#define EE 512
#define VV 30000
#define TT 20
#define LTILES 469   // ceil(VV/64)

// ---- device scratch (no cudaMalloc allowed) ----
__device__ __align__(16) float g_mean [NB*AA];
__device__ __align__(16) float g_h    [NB*HH];
__device__ __align__(16) float g_c    [NB*HH];
__device__ __align__(16) float g_hlWa [NB*LL*HH];
__device__ __align__(16) float g_hUa  [NB*HH];
__device__ __align__(16) float g_e    [NB*224];
__device__ __align__(16) float g_beta [NB];
__device__ __align__(16) float g_x    [NB*(AA+EE)];
__device__ __align__(16) float g_gpart[3*NB*4*HH];
__device__ __align__(16) int   g_tok  [NB];
__device__ __align__(16) unsigned long long g_amax[NB];

__device__ __forceinline__ float sigf(float x) { return 1.0f / (1.0f + expf(-x)); }

// ---- f32x2 helpers ----
__device__ __forceinline__ unsigned long long pk2(float x, float y) {
    unsigned long long r;
    asm("mov.b64 %0, {%1, %2};" : "=l"(r) : "f"(x), "f"(y));
    return r;
}
__device__ __forceinline__ void fma2(unsigned long long& d, unsigned long long a, unsigned long long b) {
    asm("fma.rn.f32x2 %0, %1, %2, %0;" : "+l"(d) : "l"(a), "l"(b));
}
__device__ __forceinline__ float2 upk2(unsigned long long v) {
    float2 r;
    asm("mov.b64 {%0, %1}, %2;" : "=f"(r.x), "=f"(r.y) : "l"(v));
    return r;
}
__device__ __forceinline__ unsigned int ordf(float f) {
    unsigned int u = __float_as_uint(f);
    return (u & 0x80000000u) ? ~u : (u | 0x80000000u);
}

// =====================================================================
// M=64 tiled GEMM core, f32x2 accumulate. 256 thr; 8 rows x 2 cols each.
// =====================================================================
template<int ACT>
__device__ __forceinline__ void gemm64_core(
    float (&As)[32][72], float (&Bs)[32][64],
    const float* __restrict__ A, int lda,
    const float* __restrict__ B, int ldb, int colOff,
    float* __restrict__ C, int ldc, const float* __restrict__ bias)
{
    const int tid  = threadIdx.x;
    const int lane = tid & 31, w = tid >> 5;
    const int r0   = w * 8;
    unsigned long long acc[2][4];
#pragma unroll
    for (int j = 0; j < 2; j++)
#pragma unroll
        for (int p = 0; p < 4; p++) acc[j][p] = 0ULL;

    for (int kc = 0; kc < 512; kc += 32) {
        {
            int r = tid >> 2, kb = (tid & 3) * 8;
            const float* s = A + r * lda + kc + kb;
            float4 v0 = *(const float4*)s;
            float4 v1 = *(const float4*)(s + 4);
            As[kb+0][r] = v0.x; As[kb+1][r] = v0.y; As[kb+2][r] = v0.z; As[kb+3][r] = v0.w;
            As[kb+4][r] = v1.x; As[kb+5][r] = v1.y; As[kb+6][r] = v1.z; As[kb+7][r] = v1.w;
        }
        {
            int kk = tid >> 3, cb = (tid & 7) * 8;
            const float* s = B + (kc + kk) * ldb + colOff + cb;
            *(float4*)&Bs[kk][cb]     = *(const float4*)s;
            *(float4*)&Bs[kk][cb + 4] = *(const float4*)(s + 4);
        }
        __syncthreads();
#pragma unroll
        for (int k = 0; k < 32; k++) {
            const unsigned long long* ap = (const unsigned long long*)&As[k][r0];
            unsigned long long a0 = ap[0], a1 = ap[1], a2 = ap[2], a3 = ap[3];
            float2 b = *(const float2*)&Bs[k][lane * 2];
            unsigned long long bb0 = pk2(b.x, b.x), bb1 = pk2(b.y, b.y);
            fma2(acc[0][0], a0, bb0); fma2(acc[0][1], a1, bb0);
            fma2(acc[0][2], a2, bb0); fma2(acc[0][3], a3, bb0);
            fma2(acc[1][0], a0, bb1); fma2(acc[1][1], a1, bb1);
            fma2(acc[1][2], a2, bb1); fma2(acc[1][3], a3, bb1);
        }
        __syncthreads();
    }
#pragma unroll
    for (int j = 0; j < 2; j++) {
        int col = colOff + lane * 2 + j;
        float bv = bias ? bias[col] : 0.0f;
#pragma unroll
        for (int p = 0; p < 4; p++) {
            float2 v = upk2(acc[j][p]);
            float x = v.x + bv, y = v.y + bv;
            if (ACT == 1) { x = tanhf(x); y = tanhf(y); }
            C[(r0 + 2*p    ) * ldc + col] = x;
            C[(r0 + 2*p + 1) * ldc + col] = y;
        }
    }
}

// ---- precompute ----
__global__ __launch_bounds__(256) void kernel_mean(const float* __restrict__ hl) {
    int n = blockIdx.x, tid = threadIdx.x;
    float s0 = 0.f, s1 = 0.f;
    for (int l = 0; l < LL; l++) {
        const float* row = hl + (n * LL + l) * AA;
        s0 += row[tid]; s1 += row[tid + 256];
    }
    g_mean[n * AA + tid]       = s0 / 196.0f;
    g_mean[n * AA + tid + 256] = s1 / 196.0f;
    if (tid == 0) { g_tok[n] = 1; g_amax[n] = 0ULL; }
}

__global__ __launch_bounds__(256) void kernel_init_hc(
    const float* __restrict__ Wh0, const float* __restrict__ bh0,
    const float* __restrict__ Wc0, const float* __restrict__ bc0)
{
    __shared__ __align__(16) float As[32][72];
    __shared__ __align__(16) float Bs[32][64];
    int colOff = blockIdx.x * 64;
    if (blockIdx.y == 0)
        gemm64_core<1>(As, Bs, g_mean, AA, Wh0, HH, colOff, g_h, HH, bh0);
    else
        gemm64_core<1>(As, Bs, g_mean, AA, Wc0, HH, colOff, g_c, HH, bc0);
}

__global__ __launch_bounds__(256) void kernel_hlwa(
    const float* __restrict__ hl, const float* __restrict__ Wa)
{
    __shared__ __align__(16) float As[32][72];
    __shared__ __align__(16) float Bs[32][64];
    int rowOff = blockIdx.y * 64;
    gemm64_core<0>(As, Bs, hl + rowOff * AA, AA, Wa, HH,
                   blockIdx.x * 64, g_hlWa + rowOff * HH, HH, (const float*)0);
}

// standalone hUa for step 0
__global__ __launch_bounds__(256) void kernel_hua(
    const float* __restrict__ Ua, const float* __restrict__ ba)
{
    __shared__ __align__(16) float As[32][72];
    __shared__ __align__(16) float Bs[32][64];
    gemm64_core<0>(As, Bs, g_h, HH, Ua, HH, blockIdx.x * 64, g_hUa, HH, ba);
}

// ---- e-scores: grid (64, 7), block (n, yc) does l = yc*28 .. yc*28+27 ----
__global__ __launch_bounds__(256) void kernel_escore(
    const float* __restrict__ va, const float* __restrict__ Wb,
    const float* __restrict__ bb)
{
    __shared__ float sh_u[HH], sh_va[HH];
    __shared__ float red[8];
    const int n = blockIdx.x, yc = blockIdx.y;
    const int tid = threadIdx.x, w = tid >> 5, lane = tid & 31;

    sh_u[tid]        = g_hUa[n*HH + tid];
    sh_u[tid + 256]  = g_hUa[n*HH + tid + 256];
    sh_va[tid]       = va[tid];
    sh_va[tid + 256] = va[tid + 256];

    if (yc == 0) {   // beta = sigmoid(h . Wb + bb)
        float p = g_h[n*HH + tid] * Wb[tid] + g_h[n*HH + tid + 256] * Wb[tid + 256];
#pragma unroll
        for (int o = 16; o > 0; o >>= 1) p += __shfl_xor_sync(0xffffffffu, p, o);
        if (lane == 0) red[w] = p;
    }
    __syncthreads();
    if (yc == 0 && tid == 0) {
        float s = 0.f;
#pragma unroll
        for (int i = 0; i < 8; i++) s += red[i];
        g_beta[n] = sigf(s + bb[0]);
    }

    const int l0 = yc * 28;
    for (int l = w; l < 28; l += 8) {
        const float* row = g_hlWa + (n * LL + l0 + l) * HH;
        float s = 0.f;
#pragma unroll
        for (int k = lane; k < HH; k += 32)
            s += sh_va[k] * tanhf(row[k] + sh_u[k]);
#pragma unroll
        for (int o = 16; o > 0; o >>= 1) s += __shfl_xor_sync(0xffffffffu, s, o);
        if (lane == 0) g_e[n * 224 + l0 + l] = s;
    }
}

// ---- softmax + z + emb: grid (64, 2), block (n, half) does 256 cols ----
__global__ __launch_bounds__(256) void kernel_attnz(
    const float* __restrict__ hl, const float* __restrict__ emb)
{
    __shared__ float sh_e[200];
    __shared__ float red[8];
    __shared__ float smax, ssum;
    const int n = blockIdx.x, half = blockIdx.y;
    const int tid = threadIdx.x, w = tid >> 5, lane = tid & 31;

    float ev = (tid < LL) ? g_e[n * 224 + tid] : -1e30f;
    {   // max
        float m = ev;
#pragma unroll
        for (int o = 16; o > 0; o >>= 1) m = fmaxf(m, __shfl_xor_sync(0xffffffffu, m, o));
        if (lane == 0) red[w] = m;
        __syncthreads();
        if (tid == 0) {
            float mm = red[0];
#pragma unroll
            for (int i = 1; i < 8; i++) mm = fmaxf(mm, red[i]);
            smax = mm;
        }
        __syncthreads();
    }
    float ex = (tid < LL) ? expf(ev - smax) : 0.f;
    if (tid < LL) sh_e[tid] = ex;
    {   // sum
        float s = ex;
#pragma unroll
        for (int o = 16; o > 0; o >>= 1) s += __shfl_xor_sync(0xffffffffu, s, o);
        if (lane == 0) red[w] = s;
        __syncthreads();
        if (tid == 0) {
            float ss = 0.f;
#pragma unroll
            for (int i = 0; i < 8; i++) ss += red[i];
            ssum = ss;
        }
        __syncthreads();
    }

    // z[col] = (beta/sum) * sum_l e[l]*hl[n,l,col]
    const float scale = g_beta[n] / ssum;
    const int col = half * 256 + tid;
    float s = 0.f;
#pragma unroll 7
    for (int l = 0; l < LL; l++)
        s += sh_e[l] * hl[(n * LL + l) * AA + col];
    g_x[n * (AA+EE) + col] = s * scale;

    const int tk = g_tok[n];
    g_x[n * (AA+EE) + AA + col] = emb[tk * EE + col];
}

__global__ __launch_bounds__(256) void kernel_gates(
    const float* __restrict__ Wx, const float* __restrict__ Wh)
{
    __shared__ __align__(16) float As[32][72];
    __shared__ __align__(16) float Bs[32][64];
    int z = blockIdx.y;
    const float* A; int lda; const float* B;
    if (z < 2) { A = g_x + z * 512; lda = AA + EE; B = Wx + z * 512 * (4*HH); }
    else       { A = g_h;           lda = HH;      B = Wh; }
    gemm64_core<0>(As, Bs, A, lda, B, 4*HH, blockIdx.x * 64,
                   g_gpart + z * NB * 4 * HH, 4*HH, (const float*)0);
}

__global__ __launch_bounds__(128) void kernel_lstm(const float* __restrict__ b_lstm) {
    int n = blockIdx.x;
    const float* p0 = g_gpart + 0 * NB * 4*HH + n * 4*HH;
    const float* p1 = g_gpart + 1 * NB * 4*HH + n * 4*HH;
    const float* p2 = g_gpart + 2 * NB * 4*HH + n * 4*HH;
    for (int j = threadIdx.x; j < HH; j += 128) {
        float iv = p0[j]      + p1[j]      + p2[j]      + b_lstm[j];
        float fv = p0[j+512]  + p1[j+512]  + p2[j+512]  + b_lstm[j+512];
        float gv = p0[j+1024] + p1[j+1024] + p2[j+1024] + b_lstm[j+1024];
        float ov = p0[j+1536] + p1[j+1536] + p2[j+1536] + b_lstm[j+1536];
        float c  = sigf(fv) * g_c[n*HH + j] + sigf(iv) * tanhf(gv);
        g_c[n*HH + j] = c;
        g_h[n*HH + j] = sigf(ov) * tanhf(c);
    }
}

// logits GEMM + fused argmax; blocks >= LTILES compute next step's hUa
__global__ __launch_bounds__(256) void kernel_logits(
    const float* __restrict__ Wout, const float* __restrict__ bout,
    const float* __restrict__ Ua,   const float* __restrict__ ba)
{
    __shared__ __align__(16) float As[32][72];
    __shared__ __align__(16) float Bs[32][64];
    if (blockIdx.x >= LTILES) {
        gemm64_core<0>(As, Bs, g_h, HH, Ua, HH, (blockIdx.x - LTILES) * 64,
                       g_hUa, HH, ba);
        return;
    }
    const int colOff = blockIdx.x * 64;
    const int tid = threadIdx.x;
    const int lane = tid & 31, w = tid >> 5;
    const int r0 = w * 8;
    unsigned long long acc[2][4];
#pragma unroll
    for (int j = 0; j < 2; j++)
#pragma unroll
        for (int p = 0; p < 4; p++) acc[j][p] = 0ULL;

    for (int kc = 0; kc < 512; kc += 32) {
        {
            int r = tid >> 2, kb = (tid & 3) * 8;
            const float* s = g_h + r * HH + kc + kb;
            float4 v0 = *(const float4*)s;
            float4 v1 = *(const float4*)(s + 4);
            As[kb+0][r] = v0.x; As[kb+1][r] = v0.y; As[kb+2][r] = v0.z; As[kb+3][r] = v0.w;
            As[kb+4][r] = v1.x; As[kb+5][r] = v1.y; As[kb+6][r] = v1.z; As[kb+7][r] = v1.w;
        }
        {
            int kk = tid >> 3, cb = (tid & 7) * 8;
            int col = colOff + cb;
            if (col + 8 <= VV) {
                const float* s = Wout + (kc + kk) * VV + col;
                *(float4*)&Bs[kk][cb]     = *(const float4*)s;
                *(float4*)&Bs[kk][cb + 4] = *(const float4*)(s + 4);
            } else {
                float4 z = make_float4(0.f,0.f,0.f,0.f);
                *(float4*)&Bs[kk][cb] = z; *(float4*)&Bs[kk][cb + 4] = z;
            }
        }
        __syncthreads();
#pragma unroll
        for (int k = 0; k < 32; k++) {
            const unsigned long long* ap = (const unsigned long long*)&As[k][r0];
            unsigned long long a0 = ap[0], a1 = ap[1], a2 = ap[2], a3 = ap[3];
            float2 b = *(const float2*)&Bs[k][lane * 2];
            unsigned long long bb0 = pk2(b.x, b.x), bb1 = pk2(b.y, b.y);
            fma2(acc[0][0], a0, bb0); fma2(acc[0][1], a1, bb0);
            fma2(acc[0][2], a2, bb0); fma2(acc[0][3], a3, bb0);
            fma2(acc[1][0], a0, bb1); fma2(acc[1][1], a1, bb1);
            fma2(acc[1][2], a2, bb1); fma2(acc[1][3], a3, bb1);
        }
        __syncthreads();
    }

    const int c0 = colOff + lane * 2;
    const int c1 = c0 + 1;
    const bool v0ok = (c0 < VV), v1ok = (c1 < VV);
    const float b0 = v0ok ? bout[c0] : 0.f;
    const float b1 = v1ok ? bout[c1] : 0.f;
#pragma unroll
    for (int p = 0; p < 4; p++) {
        float2 a0 = upk2(acc[0][p]);
        float2 a1 = upk2(acc[1][p]);
#pragma unroll
        for (int q = 0; q < 2; q++) {
            float va0 = (q == 0 ? a0.x : a0.y) + b0;
            float va1 = (q == 0 ? a1.x : a1.y) + b1;
            unsigned long long k0 = v0ok ?
                (((unsigned long long)ordf(va0) << 32) | (unsigned)(0xFFFFFFFFu - (unsigned)c0)) : 0ULL;
            unsigned long long k1 = v1ok ?
                (((unsigned long long)ordf(va1) << 32) | (unsigned)(0xFFFFFFFFu - (unsigned)c1)) : 0ULL;
            unsigned long long kk = k0 > k1 ? k0 : k1;
#pragma unroll
            for (int o = 16; o > 0; o >>= 1) {
                unsigned long long ot = __shfl_xor_sync(0xffffffffu, kk, o);
                if (ot > kk) kk = ot;
            }
            if (lane == 0) atomicMax(&g_amax[r0 + 2*p + q], kk);
        }
    }
}

__global__ void kernel_finalize(float* __restrict__ out, int t) {
    int n = threadIdx.x;  // 64 threads
    unsigned long long key = g_amax[n];
    int col = (int)(0xFFFFFFFFu - (unsigned)(key & 0xFFFFFFFFull));
    if (col < 0 || col >= VV) col = 0;
    g_tok[n] = col;
    out[n * TT + t] = (float)col;
    g_amax[n] = 0ULL;
}

extern "C" void kernel_launch(void* const* d_in, const int* in_sizes, int n_in,
                              void* d_out, int out_size) {
    static const int dict_sz[17] = {
        6422528, 15360000, 262144, 512, 262144, 512, 262144, 262144, 512, 512,
        512, 1, 2097152, 1048576, 2048, 15360000, 30000 };
    static const int alpha_sz[17] = {
        262144, 262144, 512, 262144, 1048576, 262144, 15360000, 2097152, 2048,
        512, 6422528, 1, 512, 512, 30000, 15360000, 512 };
    static const int alpha_map[17] = {10,15,5,13,3,12,1,0,9,16,2,11,7,4,8,6,14};

    int m[17];
    for (int i = 0; i < 17; i++) m[i] = i;
    if (n_in >= 17) {
        bool is_dict = true, is_alpha = true;
        for (int i = 0; i < 17; i++) {
            if (in_sizes[i] != dict_sz[i])  is_dict = false;
            if (in_sizes[i] != alpha_sz[i]) is_alpha = false;
        }
        if (is_dict) {
        } else if (is_alpha) {
            for (int i = 0; i < 17; i++) m[i] = alpha_map[i];
        } else {
            for (int i = 0; i < 17; i++) {
                int s = dict_sz[i], r = 0;
                for (int j = 0; j < i; j++) if (dict_sz[j] == s) r++;
                int seen = 0, pick = i;
                for (int k = 0; k < n_in && k < 64; k++) {
                    if (in_sizes[k] == s) {
                        if (seen == r) { pick = k; break; }
                        seen++;
                    }
                }
                m[i] = pick;
            }
        }
    }

    const float* hl     = (const float*)d_in[m[0]];
    const float* emb    = (const float*)d_in[m[1]];
    const float* Wh0    = (const float*)d_in[m[2]];
    const float* bh0    = (const float*)d_in[m[3]];
    const float* Wc0    = (const float*)d_in[m[4]];
    const float* bc0    = (const float*)d_in[m[5]];
    const float* Wa     = (const float*)d_in[m[6]];
    const float* Ua     = (const float*)d_in[m[7]];
    const float* ba     = (const float*)d_in[m[8]];
    const float* va     = (const float*)d_in[m[9]];
    const float* Wb     = (const float*)d_in[m[10]];
    const float* bb     = (const float*)d_in[m[11]];
    const float* Wx     = (const float*)d_in[m[12]];
    const float* Wh     = (const float*)d_in[m[13]];
    const float* b_lstm = (const float*)d_in[m[14]];
    const float* Wout   = (const float*)d_in[m[15]];
    const float* bout   = (const float*)d_in[m[16]];
    float* out = (float*)d_out;

    kernel_mean<<<NB, 256>>>(hl);
    kernel_init_hc<<<dim3(8, 2), 256>>>(Wh0, bh0, Wc0, bc0);
    kernel_hlwa<<<dim3(8, 196), 256>>>(hl, Wa);
    kernel_hua<<<8, 256>>>(Ua, ba);   // hUa for step 0

    for (int t = 0; t < TT; t++) {
        kernel_escore<<<dim3(NB, 7), 256>>>(va, Wb, bb);
        kernel_attnz<<<dim3(NB, 2), 256>>>(hl, emb);
        kernel_gates<<<dim3(32, 3), 256>>>(Wx, Wh);
        kernel_lstm<<<NB, 128>>>(b_lstm);
        kernel_logits<<<LTILES + 8, 256>>>(Wout, bout, Ua, ba);  // + hUa for t+1
        kernel_finalize<<<1, 64>>>(out, t);
    }
}